// round 5
// baseline (speedup 1.0000x reference)
#include <cuda_runtime.h>

#define DD   128
#define NN   21845          // (4^8 - 1) / 3
#define NPOS 18
#define NDEP 46
#define CS6  5461           // level_start(7)

__host__ __device__ __forceinline__ int lvl_start(int l) {
    return ((1 << (2 * l)) - 1) / 3;
}

typedef unsigned long long ull;

// packed f32x2 helpers (FFMA2: only reachable via PTX fma.rn.f32x2)
__device__ __forceinline__ ull rep2(float s) {
    ull r; asm("mov.b64 %0, {%1, %1};" : "=l"(r) : "f"(s)); return r;
}
__device__ __forceinline__ void fma2(ull& acc, ull a, ull b) {
    asm("fma.rn.f32x2 %0, %1, %2, %0;" : "+l"(acc) : "l"(a), "l"(b));
}
__device__ __forceinline__ void unpack2(ull v, float& lo, float& hi) {
    asm("mov.b64 {%0, %1}, %2;" : "=f"(lo), "=f"(hi) : "l"(v));
}

// persistent scratch (device globals: allocation-free)
__device__ float g_xz[NN * DD];            // x, then z in-place per level
__device__ int   g_pos_perm[NN];
__device__ int   g_pos_off[NPOS + 1];
__device__ int   g_pos_tg[384], g_pos_tb[384];
__device__ int   g_pos_nt;
__device__ int   g_dep_perm[NN];
__device__ int   g_dep_off[7][NDEP + 1];
__device__ int   g_dep_tg[7][320], g_dep_tb[7][320];
__device__ int   g_dep_nt[7];
// grid barrier (narrow kernel): cnt returns to 0; gen monotonic -> replay-safe
__device__ unsigned g_bar_cnt;
__device__ unsigned g_bar_gen;

__device__ __forceinline__ void gridbar(int nb) {
    __syncthreads();
    if (threadIdx.x == 0) {
        __threadfence();
        unsigned gen = *(volatile unsigned*)&g_bar_gen;
        if (atomicAdd(&g_bar_cnt, 1u) == (unsigned)nb - 1u) {
            atomicExch(&g_bar_cnt, 0u);
            __threadfence();
            atomicAdd(&g_bar_gen, 1u);
        } else {
            while (*(volatile unsigned*)&g_bar_gen == gen) __nanosleep(64);
        }
        __threadfence();
    }
    __syncthreads();
}

// ---------------------------------------------------------------------------
// Grouping: block 0 = pos, blocks 1..7 = dep level b-1
// ---------------------------------------------------------------------------
__global__ void group_kernel(const int* __restrict__ pos_ids,
                             const int* __restrict__ dep_ids) {
    __shared__ int cnt[NDEP];
    __shared__ int off[NDEP + 1];
    int t = threadIdx.x, lane = t & 31;
    const int* ids; int n, ng, base, BM;
    int *perm, *goff, *tg, *tb, *nt_out;
    if (blockIdx.x == 0) {
        ids = pos_ids; n = NN; ng = NPOS; base = 0; BM = 64;
        perm = g_pos_perm; goff = g_pos_off;
        tg = g_pos_tg; tb = g_pos_tb; nt_out = &g_pos_nt;
    } else {
        int l = blockIdx.x - 1;
        base = lvl_start(l + 1); n = 1 << (2 * (l + 1)); ng = NDEP;
        BM = (l >= 5) ? 64 : 16;
        ids = dep_ids + base; perm = g_dep_perm + base; goff = g_dep_off[l];
        tg = g_dep_tg[l]; tb = g_dep_tb[l]; nt_out = &g_dep_nt[l];
    }
    if (t < ng) cnt[t] = 0;
    __syncthreads();
    for (int i0 = 0; i0 < n; i0 += blockDim.x) {
        int i = i0 + t; bool v = (i < n);
        unsigned act = __ballot_sync(0xffffffffu, v);
        if (v) {
            int id = ids[i];
            unsigned m = __match_any_sync(act, id);
            if (lane == __ffs(m) - 1) atomicAdd(&cnt[id], __popc(m));
        }
    }
    __syncthreads();
    if (t == 0) {
        int s = 0;
        for (int j = 0; j < ng; ++j) { off[j] = s; s += cnt[j]; }
        off[ng] = s;
        int nt = 0;
        for (int j = 0; j < ng; ++j) {
            int c = off[j + 1] - off[j];
            for (int k = 0; k < c; k += BM) { tg[nt] = j; tb[nt] = off[j] + k; ++nt; }
        }
        *nt_out = nt;
        for (int j = 0; j <= ng; ++j) goff[j] = off[j];
    }
    __syncthreads();
    if (t < ng) cnt[t] = off[t];   // cursors
    __syncthreads();
    for (int i0 = 0; i0 < n; i0 += blockDim.x) {
        int i = i0 + t; bool v = (i < n);
        unsigned act = __ballot_sync(0xffffffffu, v);
        if (v) {
            int id = ids[i];
            unsigned m = __match_any_sync(act, id);
            int leader = __ffs(m) - 1;
            int prior = __popc(m & ((1u << lane) - 1u));
            int bp = 0;
            if (lane == leader) bp = atomicAdd(&cnt[id], __popc(m));
            bp = __shfl_sync(act, bp, leader);
            perm[bp + prior] = base + i;   // global node index
        }
    }
}

// ---------------------------------------------------------------------------
// Big grouped GEMM: BM=64 x BN=128, K=128 in smem, 512 threads (16 warps).
// Thread: 4 rows (ty+16i) x 4 cols (4*tx..4*tx+3) as 2 FFMA2 col-pairs.
// mode 0: srcA=emb, plain store to g_xz[node]
// mode 2: srcA=g_xz, atomicMax into parent row of g_xz
// ---------------------------------------------------------------------------
#define SMEM_BIG ((16384 + 64 * 128) * 4)

__global__ __launch_bounds__(512, 2)
void gemm_big(int mode, const float* __restrict__ Wsrc,
              const float* __restrict__ bias, const float* __restrict__ srcA,
              const int* __restrict__ nt_p, const int* __restrict__ tg,
              const int* __restrict__ tb, const int* __restrict__ off,
              const int* __restrict__ perm, int cs, int pb)
{
    int tile = blockIdx.x;
    if (tile >= *nt_p) return;
    extern __shared__ float sm[];
    float* sW = sm;            // 128x128
    float* sA = sm + 16384;    // 64x128
    __shared__ int sNode[64];
    int t = threadIdx.x;
    int j = tg[tile], b0 = tb[tile];
    int mc = off[j + 1] - b0; if (mc > 64) mc = 64;
    if (t < 64) sNode[t] = perm[b0 + min(t, mc - 1)];
    const float4* W4 = (const float4*)(Wsrc + (size_t)j * 16384);
    float4* sW4 = (float4*)sW;
#pragma unroll
    for (int i = 0; i < 8; ++i) sW4[t + 512 * i] = W4[t + 512 * i];
    __syncthreads();
    const float4* A4 = (const float4*)srcA;
#pragma unroll
    for (int i = 0; i < 4; ++i) {
        int idx = t + 512 * i; int r = idx >> 5, c = idx & 31;
        ((float4*)(sA + r * 128))[c] = A4[(size_t)sNode[r] * 32 + c];
    }
    __syncthreads();
    int tx = t & 31, ty = t >> 5;   // ty = warp 0..15
    ull acc2[4][2];
#pragma unroll
    for (int i = 0; i < 4; ++i) { acc2[i][0] = 0ull; acc2[i][1] = 0ull; }
#pragma unroll 1
    for (int k4 = 0; k4 < 32; ++k4) {
        float4 a4[4]; ulonglong2 b2[4];
#pragma unroll
        for (int i = 0; i < 4; ++i)
            a4[i] = *(const float4*)&sA[(ty + 16 * i) * 128 + 4 * k4];
#pragma unroll
        for (int kk = 0; kk < 4; ++kk)
            b2[kk] = *(const ulonglong2*)&sW[(4 * k4 + kk) * 128 + 4 * tx];
#pragma unroll
        for (int i = 0; i < 4; ++i) {
            ull a;
            a = rep2(a4[i].x); fma2(acc2[i][0], a, b2[0].x); fma2(acc2[i][1], a, b2[0].y);
            a = rep2(a4[i].y); fma2(acc2[i][0], a, b2[1].x); fma2(acc2[i][1], a, b2[1].y);
            a = rep2(a4[i].z); fma2(acc2[i][0], a, b2[2].x); fma2(acc2[i][1], a, b2[2].y);
            a = rep2(a4[i].w); fma2(acc2[i][0], a, b2[3].x); fma2(acc2[i][1], a, b2[3].y);
        }
    }
    float4 bv = *(const float4*)&bias[j * 128 + 4 * tx];
#pragma unroll
    for (int i = 0; i < 4; ++i) {
        int node = sNode[ty + 16 * i];
        float v0, v1, v2, v3;
        unpack2(acc2[i][0], v0, v1);
        unpack2(acc2[i][1], v2, v3);
        float ox = fmaxf(v0 + bv.x, 0.f);
        float oy = fmaxf(v1 + bv.y, 0.f);
        float oz = fmaxf(v2 + bv.z, 0.f);
        float ow = fmaxf(v3 + bv.w, 0.f);
        if (mode == 0) {
            float4 o; o.x = ox; o.y = oy; o.z = oz; o.w = ow;
            *(float4*)&g_xz[(size_t)node * 128 + 4 * tx] = o;
        } else {
            int parent = pb + ((node - cs) >> 2);
            int* zp = (int*)&g_xz[(size_t)parent * 128 + 4 * tx];
            // post-ReLU values >= 0: int ordering == float ordering
            atomicMax(zp + 0, __float_as_int(ox));
            atomicMax(zp + 1, __float_as_int(oy));
            atomicMax(zp + 2, __float_as_int(oz));
            atomicMax(zp + 3, __float_as_int(ow));
        }
    }
}

// ---------------------------------------------------------------------------
// Narrow persistent kernel: levels 4..0 + final copy-out.
// item = (16-row tile) x (32-col slice); 256 thr: 16 rows x 16 thr x 2 cols.
// ---------------------------------------------------------------------------
__global__ __launch_bounds__(256, 2)
void narrow_all(const float* __restrict__ Wsrc, const float* __restrict__ bias,
                float* __restrict__ out)
{
    __shared__ __align__(16) float sWn[128 * 36];
    __shared__ __align__(16) float sA2[16 * 128];
    __shared__ int sN[16];
    int t = threadIdx.x;
    int nb = gridDim.x;
    for (int l = 4; l >= 0; --l) {
        int cs = lvl_start(l + 1), pb = lvl_start(l);
        int nt = g_dep_nt[l];
        int items = nt * 4;
        const int* tg = g_dep_tg[l];
        const int* tb = g_dep_tb[l];
        const int* off = g_dep_off[l];
        for (int item = blockIdx.x; item < items; item += nb) {
            __syncthreads();
            int tile = item >> 2, slice = item & 3, c0 = slice * 32;
            int j = tg[tile], b0 = tb[tile];
            int mc = off[j + 1] - b0; if (mc > 16) mc = 16;
            if (t < 16) sN[t] = g_dep_perm[cs + b0 + min(t, mc - 1)];
#pragma unroll
            for (int i = 0; i < 4; ++i) {
                int idx = t + 256 * i; int k = idx >> 3, c4 = idx & 7;
                *(float4*)&sWn[k * 36 + 4 * c4] =
                    *(const float4*)&Wsrc[(size_t)j * 16384 + k * 128 + c0 + 4 * c4];
            }
            __syncthreads();
            const float4* Z4 = (const float4*)g_xz;
#pragma unroll
            for (int i = 0; i < 2; ++i) {
                int idx = t + 256 * i; int r = idx >> 5, c = idx & 31;
                ((float4*)(sA2 + r * 128))[c] = Z4[(size_t)sN[r] * 32 + c];
            }
            __syncthreads();
            int r = t >> 4, x16 = t & 15;
            ull acc = 0ull;
#pragma unroll 4
            for (int k = 0; k < 128; ++k) {
                ull a = rep2(sA2[r * 128 + k]);
                ull w = *(const ull*)&sWn[k * 36 + 2 * x16];
                fma2(acc, a, w);
            }
            int node = sN[r];
            int parent = pb + ((node - cs) >> 2);
            int col = c0 + 2 * x16;
            float2 bv = *(const float2*)&bias[j * 128 + col];
            float a0, a1; unpack2(acc, a0, a1);
            int* zp = (int*)&g_xz[(size_t)parent * 128 + col];
            atomicMax(zp + 0, __float_as_int(fmaxf(a0 + bv.x, 0.f)));
            atomicMax(zp + 1, __float_as_int(fmaxf(a1 + bv.y, 0.f)));
        }
        gridbar(nb);
    }
    // final: root row -> out
    if (blockIdx.x == 0 && t < 128) out[t] = g_xz[t];
}

// ---------------------------------------------------------------------------
extern "C" void kernel_launch(void* const* d_in, const int* in_sizes, int n_in,
                              void* d_out, int out_size) {
    const float* emb     = (const float*)d_in[0];
    const int*   pos_ids = (const int*)d_in[1];
    const int*   dep_ids = (const int*)d_in[2];
    const float* pos_W   = (const float*)d_in[3];
    const float* pos_b   = (const float*)d_in[4];
    const float* dep_W   = (const float*)d_in[5];
    const float* dep_b   = (const float*)d_in[6];

    cudaFuncSetAttribute(gemm_big, cudaFuncAttributeMaxDynamicSharedMemorySize,
                         SMEM_BIG);

    int *d_pos_nt, *d_pos_tg, *d_pos_tb, *d_pos_off, *d_pos_perm;
    int *d_dep_nt, *d_dep_tg, *d_dep_tb, *d_dep_off, *d_dep_perm;
    cudaGetSymbolAddress((void**)&d_pos_nt,   g_pos_nt);
    cudaGetSymbolAddress((void**)&d_pos_tg,   g_pos_tg);
    cudaGetSymbolAddress((void**)&d_pos_tb,   g_pos_tb);
    cudaGetSymbolAddress((void**)&d_pos_off,  g_pos_off);
    cudaGetSymbolAddress((void**)&d_pos_perm, g_pos_perm);
    cudaGetSymbolAddress((void**)&d_dep_nt,   g_dep_nt);
    cudaGetSymbolAddress((void**)&d_dep_tg,   g_dep_tg);
    cudaGetSymbolAddress((void**)&d_dep_tb,   g_dep_tb);
    cudaGetSymbolAddress((void**)&d_dep_off,  g_dep_off);
    cudaGetSymbolAddress((void**)&d_dep_perm, g_dep_perm);
    float* d_xz;
    cudaGetSymbolAddress((void**)&d_xz, g_xz);

    group_kernel<<<8, 1024>>>(pos_ids, dep_ids);

    // pos: all NN nodes, plain store
    gemm_big<<<360, 512, SMEM_BIG>>>(0, pos_W, pos_b, emb,
        d_pos_nt, d_pos_tg, d_pos_tb, d_pos_off, d_pos_perm, 0, 0);

    // dep level 6: 16384 children, atomicMax epilogue into level-6 parents
    gemm_big<<<302, 512, SMEM_BIG>>>(2, dep_W, dep_b, d_xz,
        d_dep_nt + 6, d_dep_tg + 6 * 320, d_dep_tb + 6 * 320,
        d_dep_off + 6 * (NDEP + 1), d_dep_perm + CS6, CS6, lvl_start(6));

    // dep level 5: 4096 children
    gemm_big<<<110, 512, SMEM_BIG>>>(2, dep_W, dep_b, d_xz,
        d_dep_nt + 5, d_dep_tg + 5 * 320, d_dep_tb + 5 * 320,
        d_dep_off + 5 * (NDEP + 1), d_dep_perm + lvl_start(6),
        lvl_start(6), lvl_start(5));

    // levels 4..0 + copy-out in one persistent kernel with grid barriers
    int dev = 0, nsm = 0, occ = 0;
    cudaGetDevice(&dev);
    cudaDeviceGetAttribute(&nsm, cudaDevAttrMultiProcessorCount, dev);
    cudaOccupancyMaxActiveBlocksPerMultiprocessor(&occ, narrow_all, 256, 0);
    if (occ < 1) occ = 1;
    int grid = nsm * (occ < 2 ? occ : 2);
    narrow_all<<<grid, 256>>>(dep_W, dep_b, (float*)d_out);
}

// round 6
// speedup vs baseline: 1.0991x; 1.0991x over previous
#include <cuda_runtime.h>

#define DD   128
#define NN   21845          // (4^8 - 1) / 3
#define NPOS 18
#define NDEP 46

__host__ __device__ __forceinline__ int lvl_start(int l) {
    return ((1 << (2 * l)) - 1) / 3;
}

typedef unsigned long long ull;

// packed f32x2 helpers (FFMA2: only reachable via PTX fma.rn.f32x2)
__device__ __forceinline__ ull rep2(float s) {
    ull r; asm("mov.b64 %0, {%1, %1};" : "=l"(r) : "f"(s)); return r;
}
__device__ __forceinline__ void fma2(ull& acc, ull a, ull b) {
    asm("fma.rn.f32x2 %0, %1, %2, %0;" : "+l"(acc) : "l"(a), "l"(b));
}
__device__ __forceinline__ void unpack2(ull v, float& lo, float& hi) {
    asm("mov.b64 {%0, %1}, %2;" : "=f"(lo), "=f"(hi) : "l"(v));
}
__device__ __forceinline__ float4 max4(float4 a, float4 b) {
    float4 r;
    r.x = fmaxf(a.x, b.x); r.y = fmaxf(a.y, b.y);
    r.z = fmaxf(a.z, b.z); r.w = fmaxf(a.w, b.w);
    return r;
}

// persistent scratch (device globals: allocation-free)
__device__ float g_xz[NN * DD];            // x from pos stage (read-only after)
__device__ float g_u[NN * DD];             // u outputs keyed by global child idx
__device__ int   g_pos_perm[NN];
__device__ int   g_pos_off[NPOS + 1];
__device__ int   g_pos_tg[384], g_pos_tb[384];
__device__ int   g_pos_nt;
__device__ int   g_dep_perm[NN];
__device__ int   g_dep_off[7][NDEP + 1];
__device__ int   g_dep_tg[7][320], g_dep_tb[7][320];
__device__ int   g_dep_nt[7];
// grid barrier: cnt returns to 0; gen monotonic -> replay-safe
__device__ unsigned g_bar_cnt;
__device__ unsigned g_bar_gen;

__device__ __forceinline__ void gridbar(int nb) {
    __syncthreads();
    if (threadIdx.x == 0) {
        __threadfence();
        unsigned gen = *(volatile unsigned*)&g_bar_gen;
        if (atomicAdd(&g_bar_cnt, 1u) == (unsigned)nb - 1u) {
            atomicExch(&g_bar_cnt, 0u);
            __threadfence();
            atomicAdd(&g_bar_gen, 1u);
        } else {
            while (*(volatile unsigned*)&g_bar_gen == gen) __nanosleep(64);
        }
        __threadfence();
    }
    __syncthreads();
}

// ---------------------------------------------------------------------------
// Grouping: block 0 = pos, blocks 1..7 = dep level b-1
// ---------------------------------------------------------------------------
__global__ void group_kernel(const int* __restrict__ pos_ids,
                             const int* __restrict__ dep_ids) {
    __shared__ int cnt[NDEP];
    __shared__ int off[NDEP + 1];
    int t = threadIdx.x, lane = t & 31;
    const int* ids; int n, ng, base, BM;
    int *perm, *goff, *tg, *tb, *nt_out;
    if (blockIdx.x == 0) {
        ids = pos_ids; n = NN; ng = NPOS; base = 0; BM = 64;
        perm = g_pos_perm; goff = g_pos_off;
        tg = g_pos_tg; tb = g_pos_tb; nt_out = &g_pos_nt;
    } else {
        int l = blockIdx.x - 1;
        base = lvl_start(l + 1); n = 1 << (2 * (l + 1)); ng = NDEP;
        BM = (l >= 5) ? 64 : 16;
        ids = dep_ids + base; perm = g_dep_perm + base; goff = g_dep_off[l];
        tg = g_dep_tg[l]; tb = g_dep_tb[l]; nt_out = &g_dep_nt[l];
    }
    if (t < ng) cnt[t] = 0;
    __syncthreads();
    for (int i0 = 0; i0 < n; i0 += blockDim.x) {
        int i = i0 + t; bool v = (i < n);
        unsigned act = __ballot_sync(0xffffffffu, v);
        if (v) {
            int id = ids[i];
            unsigned m = __match_any_sync(act, id);
            if (lane == __ffs(m) - 1) atomicAdd(&cnt[id], __popc(m));
        }
    }
    __syncthreads();
    if (t == 0) {
        int s = 0;
        for (int j = 0; j < ng; ++j) { off[j] = s; s += cnt[j]; }
        off[ng] = s;
        int nt = 0;
        for (int j = 0; j < ng; ++j) {
            int c = off[j + 1] - off[j];
            for (int k = 0; k < c; k += BM) { tg[nt] = j; tb[nt] = off[j] + k; ++nt; }
        }
        *nt_out = nt;
        for (int j = 0; j <= ng; ++j) goff[j] = off[j];
    }
    __syncthreads();
    if (t < ng) cnt[t] = off[t];   // cursors
    __syncthreads();
    for (int i0 = 0; i0 < n; i0 += blockDim.x) {
        int i = i0 + t; bool v = (i < n);
        unsigned act = __ballot_sync(0xffffffffu, v);
        if (v) {
            int id = ids[i];
            unsigned m = __match_any_sync(act, id);
            int leader = __ffs(m) - 1;
            int prior = __popc(m & ((1u << lane) - 1u));
            int bp = 0;
            if (lane == leader) bp = atomicAdd(&cnt[id], __popc(m));
            bp = __shfl_sync(act, bp, leader);
            perm[bp + prior] = base + i;   // global node index
        }
    }
}

// ---------------------------------------------------------------------------
// Big grouped GEMM: BM=64 x BN=128, K=128 in smem, 256 threads.
// Thread: 8 rows (ty+8i) x 4 cols (4*tx..4*tx+3) as 2 FFMA2 col-pairs.
// mode 0: A = emb[node],                 out: g_xz[node]   (pos)
// mode 1: A = g_xz[node] (leaf z = x),   out: g_u[node]    (dep level 6)
// mode 2: A = max(g_xz[node], u-kids),   out: g_u[node]    (dep level 5)
// ---------------------------------------------------------------------------
#define SMEM_BIG ((16384 + 64 * 128) * 4)

__global__ __launch_bounds__(256, 2)
void gemm_big(int mode, const float* __restrict__ Wsrc,
              const float* __restrict__ bias, const float* __restrict__ srcA,
              const int* __restrict__ nt_p, const int* __restrict__ tg,
              const int* __restrict__ tb, const int* __restrict__ off,
              const int* __restrict__ perm, int cs_row, int cs_child)
{
    int tile = blockIdx.x;
    if (tile >= *nt_p) return;
    extern __shared__ float sm[];
    float* sW = sm;            // 128x128
    float* sA = sm + 16384;    // 64x128
    __shared__ int sNode[64];
    int t = threadIdx.x;
    int j = tg[tile], b0 = tb[tile];
    int mc = off[j + 1] - b0; if (mc > 64) mc = 64;
    if (t < 64) sNode[t] = perm[b0 + min(t, mc - 1)];
    const float4* W4 = (const float4*)(Wsrc + (size_t)j * 16384);
    float4* sW4 = (float4*)sW;
#pragma unroll
    for (int i = 0; i < 16; ++i) sW4[t + 256 * i] = W4[t + 256 * i];
    __syncthreads();
    if (mode < 2) {
        const float4* A4 = (const float4*)srcA;
#pragma unroll
        for (int i = 0; i < 8; ++i) {
            int idx = t + 256 * i; int r = idx >> 5, c = idx & 31;
            ((float4*)(sA + r * 128))[c] = A4[(size_t)sNode[r] * 32 + c];
        }
    } else {
        // fused max-gather: z[c] = max(x[c], u[4 children])
        const float4* X4 = (const float4*)g_xz;
        const float4* U4 = (const float4*)g_u;
#pragma unroll
        for (int i = 0; i < 8; ++i) {
            int idx = t + 256 * i; int r = idx >> 5, c = idx & 31;
            int node = sNode[r];
            int ch = cs_child + 4 * (node - cs_row);
            float4 v = X4[(size_t)node * 32 + c];
            v = max4(v, U4[(size_t)(ch + 0) * 32 + c]);
            v = max4(v, U4[(size_t)(ch + 1) * 32 + c]);
            v = max4(v, U4[(size_t)(ch + 2) * 32 + c]);
            v = max4(v, U4[(size_t)(ch + 3) * 32 + c]);
            ((float4*)(sA + r * 128))[c] = v;
        }
    }
    __syncthreads();
    int tx = t & 31, ty = t >> 5;
    ull acc2[8][2];
#pragma unroll
    for (int i = 0; i < 8; ++i) { acc2[i][0] = 0ull; acc2[i][1] = 0ull; }
#pragma unroll 4
    for (int k4 = 0; k4 < 32; ++k4) {
        float4 a4[8]; ulonglong2 b2[4];
#pragma unroll
        for (int kk = 0; kk < 4; ++kk)
            b2[kk] = *(const ulonglong2*)&sW[(4 * k4 + kk) * 128 + 4 * tx];
#pragma unroll
        for (int i = 0; i < 8; ++i)
            a4[i] = *(const float4*)&sA[(ty + 8 * i) * 128 + 4 * k4];
#pragma unroll
        for (int i = 0; i < 8; ++i) {
            ull a;
            a = rep2(a4[i].x); fma2(acc2[i][0], a, b2[0].x); fma2(acc2[i][1], a, b2[0].y);
            a = rep2(a4[i].y); fma2(acc2[i][0], a, b2[1].x); fma2(acc2[i][1], a, b2[1].y);
            a = rep2(a4[i].z); fma2(acc2[i][0], a, b2[2].x); fma2(acc2[i][1], a, b2[2].y);
            a = rep2(a4[i].w); fma2(acc2[i][0], a, b2[3].x); fma2(acc2[i][1], a, b2[3].y);
        }
    }
    float4 bv = *(const float4*)&bias[j * 128 + 4 * tx];
    float* dst = (mode == 0) ? g_xz : g_u;
#pragma unroll
    for (int i = 0; i < 8; ++i) {
        int node = sNode[ty + 8 * i];
        float v0, v1, v2, v3;
        unpack2(acc2[i][0], v0, v1);
        unpack2(acc2[i][1], v2, v3);
        float4 o;
        o.x = fmaxf(v0 + bv.x, 0.f);
        o.y = fmaxf(v1 + bv.y, 0.f);
        o.z = fmaxf(v2 + bv.z, 0.f);
        o.w = fmaxf(v3 + bv.w, 0.f);
        *(float4*)&dst[(size_t)node * 128 + 4 * tx] = o;
    }
}

// ---------------------------------------------------------------------------
// Narrow persistent kernel: dep levels 4..0 (fused max-gather, STG epilogue),
// grid barrier between levels, root finalize at the end.
// item = (16-row tile) x (32-col slice); 256 thr: 16 rows x 16 thr x 2 cols.
// ---------------------------------------------------------------------------
__global__ __launch_bounds__(256, 2)
void narrow_all(const float* __restrict__ Wsrc, const float* __restrict__ bias,
                float* __restrict__ out)
{
    __shared__ __align__(16) float sWn[128 * 36];
    __shared__ __align__(16) float sA2[16 * 128];
    __shared__ int sN[16];
    int t = threadIdx.x;
    int nb = gridDim.x;
    for (int l = 4; l >= 0; --l) {
        int cs_row = lvl_start(l + 1);      // this level's children (rows)
        int cs_child = lvl_start(l + 2);    // their children (u sources)
        int nt = g_dep_nt[l];
        int items = nt * 4;
        const int* tg = g_dep_tg[l];
        const int* tb = g_dep_tb[l];
        const int* off = g_dep_off[l];
        for (int item = blockIdx.x; item < items; item += nb) {
            __syncthreads();
            int tile = item >> 2, slice = item & 3, c0 = slice * 32;
            int j = tg[tile], b0 = tb[tile];
            int mc = off[j + 1] - b0; if (mc > 16) mc = 16;
            if (t < 16) sN[t] = g_dep_perm[cs_row + b0 + min(t, mc - 1)];
#pragma unroll
            for (int i = 0; i < 4; ++i) {
                int idx = t + 256 * i; int k = idx >> 3, c4 = idx & 7;
                *(float4*)&sWn[k * 36 + 4 * c4] =
                    *(const float4*)&Wsrc[(size_t)j * 16384 + k * 128 + c0 + 4 * c4];
            }
            __syncthreads();
            const float4* X4 = (const float4*)g_xz;
            const float4* U4 = (const float4*)g_u;
#pragma unroll
            for (int i = 0; i < 2; ++i) {
                int idx = t + 256 * i; int r = idx >> 5, c = idx & 31;
                int node = sN[r];
                int ch = cs_child + 4 * (node - cs_row);
                float4 v = X4[(size_t)node * 32 + c];
                v = max4(v, U4[(size_t)(ch + 0) * 32 + c]);
                v = max4(v, U4[(size_t)(ch + 1) * 32 + c]);
                v = max4(v, U4[(size_t)(ch + 2) * 32 + c]);
                v = max4(v, U4[(size_t)(ch + 3) * 32 + c]);
                ((float4*)(sA2 + r * 128))[c] = v;
            }
            __syncthreads();
            int r = t >> 4, x16 = t & 15;
            ull acc = 0ull;
#pragma unroll 4
            for (int k = 0; k < 128; ++k) {
                ull a = rep2(sA2[r * 128 + k]);
                ull w = *(const ull*)&sWn[k * 36 + 2 * x16];
                fma2(acc, a, w);
            }
            int node = sN[r];
            int col = c0 + 2 * x16;
            float2 bv = *(const float2*)&bias[j * 128 + col];
            float a0, a1; unpack2(acc, a0, a1);
            float2 o;
            o.x = fmaxf(a0 + bv.x, 0.f);
            o.y = fmaxf(a1 + bv.y, 0.f);
            *(float2*)&g_u[(size_t)node * 128 + col] = o;
        }
        gridbar(nb);
    }
    // root finalize: out = max(x[0], u[1..4])
    if (blockIdx.x == 0 && t < 32) {
        const float4* X4 = (const float4*)g_xz;
        const float4* U4 = (const float4*)g_u;
        float4 v = X4[t];
        v = max4(v, U4[1 * 32 + t]);
        v = max4(v, U4[2 * 32 + t]);
        v = max4(v, U4[3 * 32 + t]);
        v = max4(v, U4[4 * 32 + t]);
        ((float4*)out)[t] = v;
    }
}

// ---------------------------------------------------------------------------
extern "C" void kernel_launch(void* const* d_in, const int* in_sizes, int n_in,
                              void* d_out, int out_size) {
    const float* emb     = (const float*)d_in[0];
    const int*   pos_ids = (const int*)d_in[1];
    const int*   dep_ids = (const int*)d_in[2];
    const float* pos_W   = (const float*)d_in[3];
    const float* pos_b   = (const float*)d_in[4];
    const float* dep_W   = (const float*)d_in[5];
    const float* dep_b   = (const float*)d_in[6];

    cudaFuncSetAttribute(gemm_big, cudaFuncAttributeMaxDynamicSharedMemorySize,
                         SMEM_BIG);

    int *d_pos_nt, *d_pos_tg, *d_pos_tb, *d_pos_off, *d_pos_perm;
    int *d_dep_nt, *d_dep_tg, *d_dep_tb, *d_dep_off, *d_dep_perm;
    cudaGetSymbolAddress((void**)&d_pos_nt,   g_pos_nt);
    cudaGetSymbolAddress((void**)&d_pos_tg,   g_pos_tg);
    cudaGetSymbolAddress((void**)&d_pos_tb,   g_pos_tb);
    cudaGetSymbolAddress((void**)&d_pos_off,  g_pos_off);
    cudaGetSymbolAddress((void**)&d_pos_perm, g_pos_perm);
    cudaGetSymbolAddress((void**)&d_dep_nt,   g_dep_nt);
    cudaGetSymbolAddress((void**)&d_dep_tg,   g_dep_tg);
    cudaGetSymbolAddress((void**)&d_dep_tb,   g_dep_tb);
    cudaGetSymbolAddress((void**)&d_dep_off,  g_dep_off);
    cudaGetSymbolAddress((void**)&d_dep_perm, g_dep_perm);
    float* d_xz;
    cudaGetSymbolAddress((void**)&d_xz, g_xz);

    group_kernel<<<8, 1024>>>(pos_ids, dep_ids);

    // pos: all NN nodes -> g_xz
    gemm_big<<<360, 256, SMEM_BIG>>>(0, pos_W, pos_b, emb,
        d_pos_nt, d_pos_tg, d_pos_tb, d_pos_off, d_pos_perm, 0, 0);

    // dep level 6: rows = level-7 nodes (z = x), u -> g_u
    gemm_big<<<302, 256, SMEM_BIG>>>(1, dep_W, dep_b, d_xz,
        d_dep_nt + 6, d_dep_tg + 6 * 320, d_dep_tb + 6 * 320,
        d_dep_off + 6 * (NDEP + 1), d_dep_perm + lvl_start(7),
        lvl_start(7), 0);

    // dep level 5: rows = level-6 nodes, z fused from x + u-kids, u -> g_u
    gemm_big<<<110, 256, SMEM_BIG>>>(2, dep_W, dep_b, d_xz,
        d_dep_nt + 5, d_dep_tg + 5 * 320, d_dep_tb + 5 * 320,
        d_dep_off + 5 * (NDEP + 1), d_dep_perm + lvl_start(6),
        lvl_start(6), lvl_start(7));

    // levels 4..0 + root finalize in one persistent kernel
    int dev = 0, nsm = 0, occ = 0;
    cudaGetDevice(&dev);
    cudaDeviceGetAttribute(&nsm, cudaDevAttrMultiProcessorCount, dev);
    cudaOccupancyMaxActiveBlocksPerMultiprocessor(&occ, narrow_all, 256, 0);
    if (occ < 1) occ = 1;
    int grid = nsm * (occ < 2 ? occ : 2);
    narrow_all<<<grid, 256>>>(dep_W, dep_b, (float*)d_out);
}